// round 15
// baseline (speedup 1.0000x reference)
#include <cuda_runtime.h>
#include <cuda_bf16.h>
#include <cstdint>

#define NN    8192
#define NE    65536
#define FEAT  136
#define WN    3392
#define SW_LD 68      // sH / sD row stride (floats)
#define SB_LD 72      // sB row stride (floats) -> conflict-free LDS.64 frags

__device__ float g_accum[NN * FEAT];
__device__ float g_cnt[NN];
__device__ float g_w2t[WN * 64];   // W2 transposed [n][PERM(k)], tf32 bits

// ---- SMEM layout (float offsets) ----
#define SB_HD   0                     // 128*68 = 8704 (sH during GEMM1, sD after)
#define SB_B    8704                  // 2 x 64*72 = 9216 (double-buffered B)
#define SMEM_BYTES ((8704 + 9216) * 4)   // 71680 B -> 3 CTAs/SM

// pair-permute: k and k+4 adjacent within each 8-col group
#define PERM(c) (((c) & ~7) | (((c) & 3) << 1) | (((c) >> 2) & 1))

__device__ __forceinline__ uint32_t f2tf32(float f) {
    uint32_t r;
    asm("cvt.rna.tf32.f32 %0, %1;" : "=r"(r) : "f"(f));
    return r;
}
__device__ __forceinline__ uint32_t smem_u32(const void* p) {
    uint32_t a;
    asm("{ .reg .u64 t; cvta.to.shared.u64 t, %1; cvt.u32.u64 %0, t; }" : "=r"(a) : "l"(p));
    return a;
}
#define CP_ASYNC16(dst, src) \
    asm volatile("cp.async.cg.shared.global [%0], [%1], 16;" :: "r"(dst), "l"(src))
#define CP_COMMIT() asm volatile("cp.async.commit_group;" ::: "memory")
#define CP_WAIT0()  asm volatile("cp.async.wait_group 0;" ::: "memory")

__device__ __forceinline__ void mma_tf32(float* d, const uint32_t* a, const uint32_t* b) {
    asm volatile(
        "mma.sync.aligned.m16n8k8.row.col.f32.tf32.tf32.f32 "
        "{%0,%1,%2,%3}, {%4,%5,%6,%7}, {%8,%9}, {%0,%1,%2,%3};"
        : "+f"(d[0]), "+f"(d[1]), "+f"(d[2]), "+f"(d[3])
        : "r"(a[0]), "r"(a[1]), "r"(a[2]), "r"(a[3]), "r"(b[0]), "r"(b[1]));
}

// ---------------- packed f32x2 helpers (GEMM1) ----------------
__device__ __forceinline__ unsigned long long fma2(unsigned long long a,
                                                   unsigned long long b,
                                                   unsigned long long c) {
    unsigned long long d;
    asm("fma.rn.f32x2 %0, %1, %2, %3;" : "=l"(d) : "l"(a), "l"(b), "l"(c));
    return d;
}
__device__ __forceinline__ unsigned long long add2(unsigned long long a,
                                                   unsigned long long b) {
    unsigned long long d;
    asm("add.rn.f32x2 %0, %1, %2;" : "=l"(d) : "l"(a), "l"(b));
    return d;
}
__device__ __forceinline__ float2 unpack2(unsigned long long v) {
    float2 r;
    asm("mov.b64 {%0, %1}, %2;" : "=f"(r.x), "=f"(r.y) : "l"(v));
    return r;
}
__device__ __forceinline__ float dot64(const unsigned long long* h2, const float* col) {
    const ulonglong2* c4 = reinterpret_cast<const ulonglong2*>(col);
    unsigned long long a0 = 0ull, a1 = 0ull, a2 = 0ull, a3 = 0ull;
#pragma unroll
    for (int k = 0; k < 8; k++) {
        ulonglong2 vA = c4[2*k];
        ulonglong2 vB = c4[2*k + 1];
        a0 = fma2(h2[4*k + 0], vA.x, a0);
        a1 = fma2(h2[4*k + 1], vA.y, a1);
        a2 = fma2(h2[4*k + 2], vB.x, a2);
        a3 = fma2(h2[4*k + 3], vB.y, a3);
    }
    a0 = add2(add2(a0, a1), add2(a2, a3));
    float2 f = unpack2(a0);
    return f.x + f.y;
}
__device__ __forceinline__ void stage64(const float* __restrict__ g, int ld,
                                        float* sW, int tid) {
#pragma unroll
    for (int r = 0; r < 32; r++) {
        int p = r * 128 + tid;
        sW[(p & 63) * SW_LD + (p >> 6)] = g[(p >> 6) * ld + (p & 63)];
    }
}

// ---------------- init kernel: zero accum/cnt + build W2T ----------------
__global__ void init_kernel(const float* __restrict__ w2) {
    int idx = blockIdx.x * 256 + threadIdx.x;
    if (idx < (NN * FEAT) / 4) ((float4*)g_accum)[idx] = make_float4(0.f, 0.f, 0.f, 0.f);
    if (idx < NN / 4)          ((float4*)g_cnt)[idx]   = make_float4(0.f, 0.f, 0.f, 0.f);
    if (idx < 64 * WN) {
        int k = idx / WN, n = idx % WN;
        g_w2t[n * 64 + PERM(k)] = __uint_as_float(f2tf32(w2[idx]));
    }
}

__global__ void finalize_kernel(const float* __restrict__ node_attr,
                                float* __restrict__ out) {
    int idx = blockIdx.x * 256 + threadIdx.x;     // float4 index
    if (idx < NN * 34) {
        int n = idx / 34;
        float inv = __frcp_rn(fmaxf(g_cnt[n], 1.0f));
        float4 a = ((const float4*)g_accum)[idx];
        float4 r = ((const float4*)node_attr)[idx];
        ((float4*)out)[idx] = make_float4(r.x + a.x * inv, r.y + a.y * inv,
                                          r.z + a.z * inv, r.w + a.w * inv);
    }
}

// ---------------- main fused kernel ----------------
__global__ void __launch_bounds__(128, 3) tp_edge_kernel(
    const float* __restrict__ node_attr,
    const int*   __restrict__ edge_index,
    const float* __restrict__ edge_attr,
    const float* __restrict__ edge_sh,
    const float* __restrict__ fc_w1,
    const float* __restrict__ fc_b1,
    const float* __restrict__ fc_b2)
{
    extern __shared__ float sm[];
    uint32_t* sH = (uint32_t*)(sm + SB_HD);   // GEMM1 output (tf32, PERM cols)
    float*    sD = sm + SB_HD;                // overlaid after A-frag load
    uint32_t* sB = (uint32_t*)(sm + SB_B);    // double-buffered, stride 72

    const int tid  = threadIdx.x;
    const int lane = tid & 31;
    const int w    = tid >> 5;
    const int g    = lane >> 2;
    const int t    = lane & 3;
    const int e    = blockIdx.x * 128 + tid;
    const int src  = edge_index[e];
    const int dst  = edge_index[NE + e];

    // ---------- GEMM1 (scalar fp32): h = relu(ea@W1+b1) -> sH (tf32, PERM) ----------
    {
        unsigned long long ea2[32];
        const ulonglong2* gea = reinterpret_cast<const ulonglong2*>(edge_attr + (size_t)e * 64);
#pragma unroll
        for (int k = 0; k < 16; k++) { ulonglong2 v = gea[k]; ea2[2*k] = v.x; ea2[2*k+1] = v.y; }
        float* sW = sm + SB_B;        // reuse B region before pipeline
        stage64(fc_w1, 64, sW, tid);
        __syncthreads();
#pragma unroll 1
        for (int jq = 0; jq < 16; jq++) {
#pragma unroll
            for (int u = 0; u < 4; u++) {
                int j = 4 * jq + u;
                float v = dot64(ea2, &sW[j * SW_LD]) + fc_b1[j];
                sH[tid * SW_LD + PERM(j)] = f2tf32(fmaxf(v, 0.0f));
            }
        }
    }
    __syncwarp();

    // ---------- cache A fragments in registers ----------
    uint32_t a_reg[2][8][4];
#pragma unroll
    for (int mt = 0; mt < 2; mt++)
#pragma unroll
        for (int ks = 0; ks < 8; ks++) {
            uint2 p0 = *(const uint2*)&sH[(w*32 + mt*16 + g    ) * SW_LD + ks*8 + 2*t];
            uint2 p1 = *(const uint2*)&sH[(w*32 + mt*16 + g + 8) * SW_LD + ks*8 + 2*t];
            a_reg[mt][ks][0] = p0.x; a_reg[mt][ks][1] = p1.x;
            a_reg[mt][ks][2] = p0.y; a_reg[mt][ks][3] = p1.y;
        }
    __syncwarp();
    __syncthreads();   // sW (sB region) free

    // ---------- TP input tables (local memory) ----------
    const float* na  = node_attr + (size_t)dst * FEAT;
    const float4 shv = *reinterpret_cast<const float4*>(edge_sh + 4 * (size_t)e);
    const float sh0 = shv.x, s1x = shv.y, s1y = shv.z, s1z = shv.w;
    const float INV_S3 = 0.57735026918962576f;
    const float INV_S2 = 0.70710678118654752f;

    float oA[48], oB[192], oC[120], oD[24];
#pragma unroll 1
    for (int i = 0; i < 32; i++) oA[i] = na[i] * sh0;
#pragma unroll 1
    for (int m = 0; m < 16; m++) {
        float a0 = na[32+3*m], a1 = na[33+3*m], a2 = na[34+3*m];
        oA[32+m] = (a0*s1x + a1*s1y + a2*s1z) * INV_S3;
    }
#pragma unroll 1
    for (int i = 0; i < 32; i++) {
        float v = na[i];
        oB[3*i] = v*s1x; oB[3*i+1] = v*s1y; oB[3*i+2] = v*s1z;
    }
#pragma unroll 1
    for (int m = 0; m < 16; m++) {
        int i = 32 + m;
        oB[3*i]   = na[32+3*m] * sh0;
        oB[3*i+1] = na[33+3*m] * sh0;
        oB[3*i+2] = na[34+3*m] * sh0;
    }
#pragma unroll 1
    for (int m = 0; m < 16; m++) {
        int i = 48 + m;
        float a0 = na[80+3*m], a1 = na[81+3*m], a2 = na[82+3*m];
        oB[3*i+0] = (a1*s1z - a2*s1y) * INV_S2;
        oB[3*i+1] = (a2*s1x - a0*s1z) * INV_S2;
        oB[3*i+2] = (a0*s1y - a1*s1x) * INV_S2;
    }
#pragma unroll 1
    for (int m = 0; m < 16; m++) {
        float a0 = na[32+3*m], a1 = na[33+3*m], a2 = na[34+3*m];
        oC[3*m+0] = (a1*s1z - a2*s1y) * INV_S2;
        oC[3*m+1] = (a2*s1x - a0*s1z) * INV_S2;
        oC[3*m+2] = (a0*s1y - a1*s1x) * INV_S2;
    }
#pragma unroll 1
    for (int m = 0; m < 16; m++) {
        int i = 16 + m;
        oC[3*i]   = na[80+3*m] * sh0;
        oC[3*i+1] = na[81+3*m] * sh0;
        oC[3*i+2] = na[82+3*m] * sh0;
    }
#pragma unroll 1
    for (int m = 0; m < 8; m++) {
        int i = 32 + m; float v = na[128+m];
        oC[3*i] = v*s1x; oC[3*i+1] = v*s1y; oC[3*i+2] = v*s1z;
    }
#pragma unroll 1
    for (int m = 0; m < 16; m++) {
        float a0 = na[80+3*m], a1 = na[81+3*m], a2 = na[82+3*m];
        oD[m] = (a0*s1x + a1*s1y + a2*s1z) * INV_S3;
    }
#pragma unroll 1
    for (int m = 0; m < 8; m++) oD[16+m] = na[128+m] * sh0;

    atomicAdd(&g_cnt[src], 1.0f);
    float* yacc = g_accum + (size_t)src * FEAT;
    float* sDw  = sD + w * 32 * SW_LD;

    float acc[48];
#pragma unroll
    for (int i = 0; i < 48; i++) acc[i] = 0.0f;

    const uint32_t sB_base = smem_u32(sB);

    // prologue: async-copy chunk 0 into buffer 0
    {
#pragma unroll
        for (int i = 0; i < 8; i++) {
            int idx = i * 128 + tid;
            int n = idx >> 4, j = idx & 15;
            const float* srcp = g_w2t + (size_t)n * 64 + j * 4;
            CP_ASYNC16(sB_base + n * (SB_LD * 4) + j * 16, srcp);
        }
        CP_COMMIT();
    }

    // ---------------- 53 N-chunks of 64 ----------------
#pragma unroll 1
    for (int c = 0; c < 53; c++) {
        CP_WAIT0();
        __syncthreads();                 // chunk c visible; prev reads done

        if (c + 1 < 53) {                // async-prefetch chunk c+1 (other buffer)
            uint32_t dbase = sB_base + ((c + 1) & 1) * (64 * SB_LD * 4);
#pragma unroll
            for (int i = 0; i < 8; i++) {
                int idx = i * 128 + tid;
                int n = idx >> 4, j = idx & 15;
                const float* srcp = g_w2t + ((size_t)(c + 1) * 64 + n) * 64 + j * 4;
                CP_ASYNC16(dbase + n * (SB_LD * 4) + j * 16, srcp);
            }
            CP_COMMIT();
        }

        const uint32_t* sBc = sB + (c & 1) * (64 * SB_LD);

        // accumulators init with bias from global (L1-resident broadcast)
        float d[2][8][4];
#pragma unroll
        for (int nt = 0; nt < 8; nt++) {
            float2 bp = __ldg((const float2*)&fc_b2[c * 64 + nt * 8 + 2 * t]);
#pragma unroll
            for (int mt = 0; mt < 2; mt++) {
                d[mt][nt][0] = bp.x; d[mt][nt][1] = bp.y;
                d[mt][nt][2] = bp.x; d[mt][nt][3] = bp.y;
            }
        }

        // MMA mainloop: K=64 in 8 steps, A from registers, B conflict-free
#pragma unroll
        for (int ks = 0; ks < 8; ks++) {
            uint32_t b[8][2];
#pragma unroll
            for (int nt = 0; nt < 8; nt++) {
                uint2 pb = *(const uint2*)&sBc[(nt*8 + g) * SB_LD + ks*8 + 2*t];
                b[nt][0] = pb.x; b[nt][1] = pb.y;
            }
#pragma unroll
            for (int mt = 0; mt < 2; mt++)
#pragma unroll
                for (int nt = 0; nt < 8; nt++)
                    mma_tf32(d[mt][nt], a_reg[mt][ks], b[nt]);
        }

        // fragments -> warp-private SMEM slice
#pragma unroll
        for (int mt = 0; mt < 2; mt++)
#pragma unroll
            for (int nt = 0; nt < 8; nt++) {
                *(float2*)&sDw[(mt*16 + g    ) * SW_LD + nt*8 + 2*t] = make_float2(d[mt][nt][0], d[mt][nt][1]);
                *(float2*)&sDw[(mt*16 + g + 8) * SW_LD + nt*8 + 2*t] = make_float2(d[mt][nt][2], d[mt][nt][3]);
            }
        __syncwarp();

        // own edge's 64 w-values (bias included); stride-68 LDS.128 conflict-free
        float wv[64];
#pragma unroll
        for (int u = 0; u < 16; u++) {
            float4 v = *(const float4*)&sDw[lane * SW_LD + 4 * u];
            wv[4*u] = v.x; wv[4*u+1] = v.y; wv[4*u+2] = v.z; wv[4*u+3] = v.w;
        }
        __syncwarp();

        // ---- TP contraction (register accumulators) ----
        if (c < 24) {                         // 0e
            float a0 = oA[2*c], a1 = oA[2*c + 1];
#pragma unroll
            for (int s = 0; s < 32; s++) acc[s] += a0 * wv[s] + a1 * wv[32 + s];
        } else if (c < 40) {                  // 1o
            int ib = 4 * (c - 24);
            float bx[4], by[4], bz[4];
#pragma unroll
            for (int u = 0; u < 4; u++) {
                bx[u] = oB[3*(ib+u)]; by[u] = oB[3*(ib+u)+1]; bz[u] = oB[3*(ib+u)+2];
            }
#pragma unroll
            for (int u = 0; u < 4; u++)
#pragma unroll
                for (int tt = 0; tt < 16; tt++) {
                    float wt = wv[u*16 + tt];
                    acc[tt*3+0] += bx[u] * wt; acc[tt*3+1] += by[u] * wt; acc[tt*3+2] += bz[u] * wt;
                }
        } else if (c < 50) {                  // 1e
            int ib = 4 * (c - 40);
            float bx[4], by[4], bz[4];
#pragma unroll
            for (int u = 0; u < 4; u++) {
                bx[u] = oC[3*(ib+u)]; by[u] = oC[3*(ib+u)+1]; bz[u] = oC[3*(ib+u)+2];
            }
#pragma unroll
            for (int u = 0; u < 4; u++)
#pragma unroll
                for (int tt = 0; tt < 16; tt++) {
                    float wt = wv[u*16 + tt];
                    acc[tt*3+0] += bx[u] * wt; acc[tt*3+1] += by[u] * wt; acc[tt*3+2] += bz[u] * wt;
                }
        } else {                              // 0o
            int ib = 8 * (c - 50);
            float av[8];
#pragma unroll
            for (int u = 0; u < 8; u++) av[u] = oD[ib + u];
#pragma unroll
            for (int u = 0; u < 8; u++)
#pragma unroll
                for (int tt = 0; tt < 8; tt++) acc[tt] += av[u] * wv[u*8 + tt];
        }

        // phase-boundary flushes (fully unrolled -> acc stays in registers)
        if (c == 23) {
#pragma unroll
            for (int o = 0; o < 32; o++) atomicAdd(yacc + o, acc[o] * 0.14433756729740643f);
#pragma unroll
            for (int i = 0; i < 48; i++) acc[i] = 0.0f;
        } else if (c == 39) {
#pragma unroll
            for (int q = 0; q < 48; q++) atomicAdd(yacc + 32 + q, acc[q] * 0.125f);
#pragma unroll
            for (int i = 0; i < 48; i++) acc[i] = 0.0f;
        } else if (c == 49) {
#pragma unroll
            for (int q = 0; q < 48; q++) atomicAdd(yacc + 80 + q, acc[q] * 0.15811388300841897f);
#pragma unroll
            for (int i = 0; i < 48; i++) acc[i] = 0.0f;
        } else if (c == 52) {
#pragma unroll
            for (int o = 0; o < 8; o++) atomicAdd(yacc + 128 + o, acc[o] * 0.20412414523193150f);
        }
    }
}

extern "C" void kernel_launch(void* const* d_in, const int* in_sizes, int n_in,
                              void* d_out, int out_size) {
    const float* node_attr  = (const float*)d_in[0];
    const int*   edge_index = (const int*)  d_in[1];
    const float* edge_attr  = (const float*)d_in[2];
    const float* edge_sh    = (const float*)d_in[3];
    const float* fc_w1      = (const float*)d_in[4];
    const float* fc_b1      = (const float*)d_in[5];
    const float* fc_w2      = (const float*)d_in[6];
    const float* fc_b2      = (const float*)d_in[7];
    float* out = (float*)d_out;

    cudaFuncSetAttribute(tp_edge_kernel, cudaFuncAttributeMaxDynamicSharedMemorySize, SMEM_BYTES);

    init_kernel<<<((NN * FEAT) / 4 + 255) / 256, 256>>>(fc_w2);
    tp_edge_kernel<<<NE / 128, 128, SMEM_BYTES>>>(node_attr, edge_index, edge_attr,
                                                  edge_sh, fc_w1, fc_b1, fc_b2);
    finalize_kernel<<<(NN * 34 + 255) / 256, 256>>>(node_attr, out);
}

// round 16
// speedup vs baseline: 1.0002x; 1.0002x over previous
#include <cuda_runtime.h>
#include <cuda_bf16.h>
#include <cstdint>

#define NN    8192
#define NE    65536
#define FEAT  136
#define WN    3392
#define SW_LD 68      // sH / sD row stride (floats)
#define SB_LD 72      // sB row stride (floats) -> conflict-free LDS.64 frags

__device__ float g_accum[NN * FEAT];
__device__ float g_cnt[NN];
__device__ float g_w2t[WN * 64];   // W2 transposed [n][PERM(k)], tf32 bits

// ---- SMEM layout (float offsets) ----
#define SB_HD   0                     // 128*68 = 8704 (sH during GEMM1, sD after)
#define SB_B    8704                  // 2 x 64*72 = 9216 (double-buffered B)
#define SMEM_BYTES ((8704 + 9216) * 4)   // 71680 B -> 3 CTAs/SM

// pair-permute: k and k+4 adjacent within each 8-col group
#define PERM(c) (((c) & ~7) | (((c) & 3) << 1) | (((c) >> 2) & 1))

__device__ __forceinline__ uint32_t f2tf32(float f) {
    uint32_t r;
    asm("cvt.rna.tf32.f32 %0, %1;" : "=r"(r) : "f"(f));
    return r;
}
__device__ __forceinline__ uint32_t smem_u32(const void* p) {
    uint32_t a;
    asm("{ .reg .u64 t; cvta.to.shared.u64 t, %1; cvt.u32.u64 %0, t; }" : "=r"(a) : "l"(p));
    return a;
}
#define CP_ASYNC16(dst, src) \
    asm volatile("cp.async.cg.shared.global [%0], [%1], 16;" :: "r"(dst), "l"(src))
#define CP_COMMIT() asm volatile("cp.async.commit_group;" ::: "memory")
#define CP_WAIT0()  asm volatile("cp.async.wait_group 0;" ::: "memory")

__device__ __forceinline__ void mma_tf32(float* d, const uint32_t* a, const uint32_t* b) {
    asm volatile(
        "mma.sync.aligned.m16n8k8.row.col.f32.tf32.tf32.f32 "
        "{%0,%1,%2,%3}, {%4,%5,%6,%7}, {%8,%9}, {%0,%1,%2,%3};"
        : "+f"(d[0]), "+f"(d[1]), "+f"(d[2]), "+f"(d[3])
        : "r"(a[0]), "r"(a[1]), "r"(a[2]), "r"(a[3]), "r"(b[0]), "r"(b[1]));
}

// ---------------- packed f32x2 helpers (GEMM1) ----------------
__device__ __forceinline__ unsigned long long fma2(unsigned long long a,
                                                   unsigned long long b,
                                                   unsigned long long c) {
    unsigned long long d;
    asm("fma.rn.f32x2 %0, %1, %2, %3;" : "=l"(d) : "l"(a), "l"(b), "l"(c));
    return d;
}
__device__ __forceinline__ unsigned long long add2(unsigned long long a,
                                                   unsigned long long b) {
    unsigned long long d;
    asm("add.rn.f32x2 %0, %1, %2;" : "=l"(d) : "l"(a), "l"(b));
    return d;
}
__device__ __forceinline__ float2 unpack2(unsigned long long v) {
    float2 r;
    asm("mov.b64 {%0, %1}, %2;" : "=f"(r.x), "=f"(r.y) : "l"(v));
    return r;
}
__device__ __forceinline__ float dot64(const unsigned long long* h2, const float* col) {
    const ulonglong2* c4 = reinterpret_cast<const ulonglong2*>(col);
    unsigned long long a0 = 0ull, a1 = 0ull, a2 = 0ull, a3 = 0ull;
#pragma unroll
    for (int k = 0; k < 8; k++) {
        ulonglong2 vA = c4[2*k];
        ulonglong2 vB = c4[2*k + 1];
        a0 = fma2(h2[4*k + 0], vA.x, a0);
        a1 = fma2(h2[4*k + 1], vA.y, a1);
        a2 = fma2(h2[4*k + 2], vB.x, a2);
        a3 = fma2(h2[4*k + 3], vB.y, a3);
    }
    a0 = add2(add2(a0, a1), add2(a2, a3));
    float2 f = unpack2(a0);
    return f.x + f.y;
}
__device__ __forceinline__ void stage64(const float* __restrict__ g, int ld,
                                        float* sW, int tid) {
#pragma unroll
    for (int r = 0; r < 32; r++) {
        int p = r * 128 + tid;
        sW[(p & 63) * SW_LD + (p >> 6)] = g[(p >> 6) * ld + (p & 63)];
    }
}

// ---------------- init kernel: zero accum/cnt + build W2T ----------------
__global__ void init_kernel(const float* __restrict__ w2) {
    int idx = blockIdx.x * 256 + threadIdx.x;
    if (idx < (NN * FEAT) / 4) ((float4*)g_accum)[idx] = make_float4(0.f, 0.f, 0.f, 0.f);
    if (idx < NN / 4)          ((float4*)g_cnt)[idx]   = make_float4(0.f, 0.f, 0.f, 0.f);
    if (idx < 64 * WN) {
        int k = idx / WN, n = idx % WN;
        g_w2t[n * 64 + PERM(k)] = __uint_as_float(f2tf32(w2[idx]));
    }
}

__global__ void finalize_kernel(const float* __restrict__ node_attr,
                                float* __restrict__ out) {
    int idx = blockIdx.x * 256 + threadIdx.x;     // float4 index
    if (idx < NN * 34) {
        int n = idx / 34;
        float inv = __frcp_rn(fmaxf(g_cnt[n], 1.0f));
        float4 a = ((const float4*)g_accum)[idx];
        float4 r = ((const float4*)node_attr)[idx];
        ((float4*)out)[idx] = make_float4(r.x + a.x * inv, r.y + a.y * inv,
                                          r.z + a.z * inv, r.w + a.w * inv);
    }
}

// ---------------- main fused kernel ----------------
__global__ void __launch_bounds__(128, 3) tp_edge_kernel(
    const float* __restrict__ node_attr,
    const int*   __restrict__ edge_index,
    const float* __restrict__ edge_attr,
    const float* __restrict__ edge_sh,
    const float* __restrict__ fc_w1,
    const float* __restrict__ fc_b1,
    const float* __restrict__ fc_b2)
{
    extern __shared__ float sm[];
    uint32_t* sH = (uint32_t*)(sm + SB_HD);   // GEMM1 output (tf32, PERM cols)
    float*    sD = sm + SB_HD;                // overlaid after A-frag load
    uint32_t* sB = (uint32_t*)(sm + SB_B);    // double-buffered, stride 72

    const int tid  = threadIdx.x;
    const int lane = tid & 31;
    const int w    = tid >> 5;
    const int g    = lane >> 2;
    const int t    = lane & 3;
    const int e    = blockIdx.x * 128 + tid;
    const int src  = edge_index[e];
    const int dst  = edge_index[NE + e];

    // ---------- GEMM1 (scalar fp32): h = relu(ea@W1+b1) -> sH (tf32, PERM) ----------
    {
        unsigned long long ea2[32];
        const ulonglong2* gea = reinterpret_cast<const ulonglong2*>(edge_attr + (size_t)e * 64);
#pragma unroll
        for (int k = 0; k < 16; k++) { ulonglong2 v = gea[k]; ea2[2*k] = v.x; ea2[2*k+1] = v.y; }
        float* sW = sm + SB_B;        // reuse B region before pipeline
        stage64(fc_w1, 64, sW, tid);
        __syncthreads();
#pragma unroll 1
        for (int jq = 0; jq < 16; jq++) {
#pragma unroll
            for (int u = 0; u < 4; u++) {
                int j = 4 * jq + u;
                float v = dot64(ea2, &sW[j * SW_LD]) + fc_b1[j];
                sH[tid * SW_LD + PERM(j)] = f2tf32(fmaxf(v, 0.0f));
            }
        }
    }
    __syncwarp();

    // ---------- cache A fragments in registers ----------
    uint32_t a_reg[2][8][4];
#pragma unroll
    for (int mt = 0; mt < 2; mt++)
#pragma unroll
        for (int ks = 0; ks < 8; ks++) {
            uint2 p0 = *(const uint2*)&sH[(w*32 + mt*16 + g    ) * SW_LD + ks*8 + 2*t];
            uint2 p1 = *(const uint2*)&sH[(w*32 + mt*16 + g + 8) * SW_LD + ks*8 + 2*t];
            a_reg[mt][ks][0] = p0.x; a_reg[mt][ks][1] = p1.x;
            a_reg[mt][ks][2] = p0.y; a_reg[mt][ks][3] = p1.y;
        }
    __syncwarp();
    __syncthreads();   // sW (sB region) free

    // ---------- TP input tables (local memory) ----------
    const float* na  = node_attr + (size_t)dst * FEAT;
    const float4 shv = *reinterpret_cast<const float4*>(edge_sh + 4 * (size_t)e);
    const float sh0 = shv.x, s1x = shv.y, s1y = shv.z, s1z = shv.w;
    const float INV_S3 = 0.57735026918962576f;
    const float INV_S2 = 0.70710678118654752f;

    float oA[48], oB[192], oC[120], oD[24];
#pragma unroll 1
    for (int i = 0; i < 32; i++) oA[i] = na[i] * sh0;
#pragma unroll 1
    for (int m = 0; m < 16; m++) {
        float a0 = na[32+3*m], a1 = na[33+3*m], a2 = na[34+3*m];
        oA[32+m] = (a0*s1x + a1*s1y + a2*s1z) * INV_S3;
    }
#pragma unroll 1
    for (int i = 0; i < 32; i++) {
        float v = na[i];
        oB[3*i] = v*s1x; oB[3*i+1] = v*s1y; oB[3*i+2] = v*s1z;
    }
#pragma unroll 1
    for (int m = 0; m < 16; m++) {
        int i = 32 + m;
        oB[3*i]   = na[32+3*m] * sh0;
        oB[3*i+1] = na[33+3*m] * sh0;
        oB[3*i+2] = na[34+3*m] * sh0;
    }
#pragma unroll 1
    for (int m = 0; m < 16; m++) {
        int i = 48 + m;
        float a0 = na[80+3*m], a1 = na[81+3*m], a2 = na[82+3*m];
        oB[3*i+0] = (a1*s1z - a2*s1y) * INV_S2;
        oB[3*i+1] = (a2*s1x - a0*s1z) * INV_S2;
        oB[3*i+2] = (a0*s1y - a1*s1x) * INV_S2;
    }
#pragma unroll 1
    for (int m = 0; m < 16; m++) {
        float a0 = na[32+3*m], a1 = na[33+3*m], a2 = na[34+3*m];
        oC[3*m+0] = (a1*s1z - a2*s1y) * INV_S2;
        oC[3*m+1] = (a2*s1x - a0*s1z) * INV_S2;
        oC[3*m+2] = (a0*s1y - a1*s1x) * INV_S2;
    }
#pragma unroll 1
    for (int m = 0; m < 16; m++) {
        int i = 16 + m;
        oC[3*i]   = na[80+3*m] * sh0;
        oC[3*i+1] = na[81+3*m] * sh0;
        oC[3*i+2] = na[82+3*m] * sh0;
    }
#pragma unroll 1
    for (int m = 0; m < 8; m++) {
        int i = 32 + m; float v = na[128+m];
        oC[3*i] = v*s1x; oC[3*i+1] = v*s1y; oC[3*i+2] = v*s1z;
    }
#pragma unroll 1
    for (int m = 0; m < 16; m++) {
        float a0 = na[80+3*m], a1 = na[81+3*m], a2 = na[82+3*m];
        oD[m] = (a0*s1x + a1*s1y + a2*s1z) * INV_S3;
    }
#pragma unroll 1
    for (int m = 0; m < 8; m++) oD[16+m] = na[128+m] * sh0;

    atomicAdd(&g_cnt[src], 1.0f);
    float* yacc = g_accum + (size_t)src * FEAT;
    float* sDw  = sD + w * 32 * SW_LD;

    float acc[48];
#pragma unroll
    for (int i = 0; i < 48; i++) acc[i] = 0.0f;

    const uint32_t sB_base = smem_u32(sB);

    // prologue: async-copy chunk 0 into buffer 0
    {
#pragma unroll
        for (int i = 0; i < 8; i++) {
            int idx = i * 128 + tid;
            int n = idx >> 4, j = idx & 15;
            const float* srcp = g_w2t + (size_t)n * 64 + j * 4;
            CP_ASYNC16(sB_base + n * (SB_LD * 4) + j * 16, srcp);
        }
        CP_COMMIT();
    }

    // ---------------- 53 N-chunks of 64 ----------------
#pragma unroll 1
    for (int c = 0; c < 53; c++) {
        CP_WAIT0();
        __syncthreads();                 // chunk c visible; prev reads done

        if (c + 1 < 53) {                // async-prefetch chunk c+1 (other buffer)
            uint32_t dbase = sB_base + ((c + 1) & 1) * (64 * SB_LD * 4);
#pragma unroll
            for (int i = 0; i < 8; i++) {
                int idx = i * 128 + tid;
                int n = idx >> 4, j = idx & 15;
                const float* srcp = g_w2t + ((size_t)(c + 1) * 64 + n) * 64 + j * 4;
                CP_ASYNC16(dbase + n * (SB_LD * 4) + j * 16, srcp);
            }
            CP_COMMIT();
        }

        const uint32_t* sBc = sB + (c & 1) * (64 * SB_LD);

        // accumulators init with bias from global (L1-resident broadcast)
        float d[2][8][4];
#pragma unroll
        for (int nt = 0; nt < 8; nt++) {
            float2 bp = __ldg((const float2*)&fc_b2[c * 64 + nt * 8 + 2 * t]);
#pragma unroll
            for (int mt = 0; mt < 2; mt++) {
                d[mt][nt][0] = bp.x; d[mt][nt][1] = bp.y;
                d[mt][nt][2] = bp.x; d[mt][nt][3] = bp.y;
            }
        }

        // MMA mainloop: K=64 in 8 steps, A from registers, B conflict-free
#pragma unroll
        for (int ks = 0; ks < 8; ks++) {
            uint32_t b[8][2];
#pragma unroll
            for (int nt = 0; nt < 8; nt++) {
                uint2 pb = *(const uint2*)&sBc[(nt*8 + g) * SB_LD + ks*8 + 2*t];
                b[nt][0] = pb.x; b[nt][1] = pb.y;
            }
#pragma unroll
            for (int mt = 0; mt < 2; mt++)
#pragma unroll
                for (int nt = 0; nt < 8; nt++)
                    mma_tf32(d[mt][nt], a_reg[mt][ks], b[nt]);
        }

        // fragments -> warp-private SMEM slice
#pragma unroll
        for (int mt = 0; mt < 2; mt++)
#pragma unroll
            for (int nt = 0; nt < 8; nt++) {
                *(float2*)&sDw[(mt*16 + g    ) * SW_LD + nt*8 + 2*t] = make_float2(d[mt][nt][0], d[mt][nt][1]);
                *(float2*)&sDw[(mt*16 + g + 8) * SW_LD + nt*8 + 2*t] = make_float2(d[mt][nt][2], d[mt][nt][3]);
            }
        __syncwarp();

        // own edge's 64 w-values (bias included); stride-68 LDS.128 conflict-free
        float wv[64];
#pragma unroll
        for (int u = 0; u < 16; u++) {
            float4 v = *(const float4*)&sDw[lane * SW_LD + 4 * u];
            wv[4*u] = v.x; wv[4*u+1] = v.y; wv[4*u+2] = v.z; wv[4*u+3] = v.w;
        }
        __syncwarp();

        // ---- TP contraction (register accumulators) ----
        if (c < 24) {                         // 0e
            float a0 = oA[2*c], a1 = oA[2*c + 1];
#pragma unroll
            for (int s = 0; s < 32; s++) acc[s] += a0 * wv[s] + a1 * wv[32 + s];
        } else if (c < 40) {                  // 1o
            int ib = 4 * (c - 24);
            float bx[4], by[4], bz[4];
#pragma unroll
            for (int u = 0; u < 4; u++) {
                bx[u] = oB[3*(ib+u)]; by[u] = oB[3*(ib+u)+1]; bz[u] = oB[3*(ib+u)+2];
            }
#pragma unroll
            for (int u = 0; u < 4; u++)
#pragma unroll
                for (int tt = 0; tt < 16; tt++) {
                    float wt = wv[u*16 + tt];
                    acc[tt*3+0] += bx[u] * wt; acc[tt*3+1] += by[u] * wt; acc[tt*3+2] += bz[u] * wt;
                }
        } else if (c < 50) {                  // 1e
            int ib = 4 * (c - 40);
            float bx[4], by[4], bz[4];
#pragma unroll
            for (int u = 0; u < 4; u++) {
                bx[u] = oC[3*(ib+u)]; by[u] = oC[3*(ib+u)+1]; bz[u] = oC[3*(ib+u)+2];
            }
#pragma unroll
            for (int u = 0; u < 4; u++)
#pragma unroll
                for (int tt = 0; tt < 16; tt++) {
                    float wt = wv[u*16 + tt];
                    acc[tt*3+0] += bx[u] * wt; acc[tt*3+1] += by[u] * wt; acc[tt*3+2] += bz[u] * wt;
                }
        } else {                              // 0o
            int ib = 8 * (c - 50);
            float av[8];
#pragma unroll
            for (int u = 0; u < 8; u++) av[u] = oD[ib + u];
#pragma unroll
            for (int u = 0; u < 8; u++)
#pragma unroll
                for (int tt = 0; tt < 8; tt++) acc[tt] += av[u] * wv[u*8 + tt];
        }

        // phase-boundary flushes (fully unrolled -> acc stays in registers)
        if (c == 23) {
#pragma unroll
            for (int o = 0; o < 32; o++) atomicAdd(yacc + o, acc[o] * 0.14433756729740643f);
#pragma unroll
            for (int i = 0; i < 48; i++) acc[i] = 0.0f;
        } else if (c == 39) {
#pragma unroll
            for (int q = 0; q < 48; q++) atomicAdd(yacc + 32 + q, acc[q] * 0.125f);
#pragma unroll
            for (int i = 0; i < 48; i++) acc[i] = 0.0f;
        } else if (c == 49) {
#pragma unroll
            for (int q = 0; q < 48; q++) atomicAdd(yacc + 80 + q, acc[q] * 0.15811388300841897f);
#pragma unroll
            for (int i = 0; i < 48; i++) acc[i] = 0.0f;
        } else if (c == 52) {
#pragma unroll
            for (int o = 0; o < 8; o++) atomicAdd(yacc + 128 + o, acc[o] * 0.20412414523193150f);
        }
    }
}

extern "C" void kernel_launch(void* const* d_in, const int* in_sizes, int n_in,
                              void* d_out, int out_size) {
    const float* node_attr  = (const float*)d_in[0];
    const int*   edge_index = (const int*)  d_in[1];
    const float* edge_attr  = (const float*)d_in[2];
    const float* edge_sh    = (const float*)d_in[3];
    const float* fc_w1      = (const float*)d_in[4];
    const float* fc_b1      = (const float*)d_in[5];
    const float* fc_w2      = (const float*)d_in[6];
    const float* fc_b2      = (const float*)d_in[7];
    float* out = (float*)d_out;

    cudaFuncSetAttribute(tp_edge_kernel, cudaFuncAttributeMaxDynamicSharedMemorySize, SMEM_BYTES);

    init_kernel<<<((NN * FEAT) / 4 + 255) / 256, 256>>>(fc_w2);
    tp_edge_kernel<<<NE / 128, 128, SMEM_BYTES>>>(node_attr, edge_index, edge_attr,
                                                  edge_sh, fc_w1, fc_b1, fc_b2);
    finalize_kernel<<<(NN * 34 + 255) / 256, 256>>>(node_attr, out);
}

// round 17
// speedup vs baseline: 1.4925x; 1.4921x over previous
#include <cuda_runtime.h>
#include <cuda_bf16.h>
#include <cstdint>

#define NN    8192
#define NE    65536
#define FEAT  136
#define WN    3392
#define SW_LD 68      // sH / sD row stride (floats): lane-linear LDS.128 conflict-free
#define SB_LD 72      // sB row stride (floats): (g,t) LDS.64 fragment loads conflict-free

__device__ float g_accum[NN * FEAT];
__device__ float g_cnt[NN];
__device__ float g_w2t[WN * 64];   // W2 transposed [n][PERM(k)], tf32 bits

// ---- SMEM layout (float offsets) ----
#define SB_BIAS 0                     // 3392 floats
#define SB_HD   3392                  // 128*68 = 8704 (sH during GEMM1, sD after)
#define SB_B    12096                 // 2 x 64*72 = 9216 (double-buffered B)
#define SMEM_BYTES ((12096 + 9216) * 4)   // 85248 B -> 2 CTAs/SM

// pair-permute: k and k+4 adjacent within each 8-col group
#define PERM(c) (((c) & ~7) | (((c) & 3) << 1) | (((c) >> 2) & 1))

__device__ __forceinline__ uint32_t f2tf32(float f) {
    uint32_t r;
    asm("cvt.rna.tf32.f32 %0, %1;" : "=r"(r) : "f"(f));
    return r;
}
__device__ __forceinline__ uint32_t smem_u32(const void* p) {
    uint32_t a;
    asm("{ .reg .u64 t; cvta.to.shared.u64 t, %1; cvt.u32.u64 %0, t; }" : "=r"(a) : "l"(p));
    return a;
}
#define CP_ASYNC16(dst, src) \
    asm volatile("cp.async.cg.shared.global [%0], [%1], 16;" :: "r"(dst), "l"(src))
#define CP_COMMIT() asm volatile("cp.async.commit_group;" ::: "memory")
#define CP_WAIT0()  asm volatile("cp.async.wait_group 0;" ::: "memory")

__device__ __forceinline__ void mma_tf32(float* d, const uint32_t* a, const uint32_t* b) {
    asm volatile(
        "mma.sync.aligned.m16n8k8.row.col.f32.tf32.tf32.f32 "
        "{%0,%1,%2,%3}, {%4,%5,%6,%7}, {%8,%9}, {%0,%1,%2,%3};"
        : "+f"(d[0]), "+f"(d[1]), "+f"(d[2]), "+f"(d[3])
        : "r"(a[0]), "r"(a[1]), "r"(a[2]), "r"(a[3]), "r"(b[0]), "r"(b[1]));
}

// ---------------- packed f32x2 helpers (GEMM1) ----------------
__device__ __forceinline__ unsigned long long fma2(unsigned long long a,
                                                   unsigned long long b,
                                                   unsigned long long c) {
    unsigned long long d;
    asm("fma.rn.f32x2 %0, %1, %2, %3;" : "=l"(d) : "l"(a), "l"(b), "l"(c));
    return d;
}
__device__ __forceinline__ unsigned long long add2(unsigned long long a,
                                                   unsigned long long b) {
    unsigned long long d;
    asm("add.rn.f32x2 %0, %1, %2;" : "=l"(d) : "l"(a), "l"(b));
    return d;
}
__device__ __forceinline__ float2 unpack2(unsigned long long v) {
    float2 r;
    asm("mov.b64 {%0, %1}, %2;" : "=f"(r.x), "=f"(r.y) : "l"(v));
    return r;
}
__device__ __forceinline__ float dot64(const unsigned long long* h2, const float* col) {
    const ulonglong2* c4 = reinterpret_cast<const ulonglong2*>(col);
    unsigned long long a0 = 0ull, a1 = 0ull, a2 = 0ull, a3 = 0ull;
#pragma unroll
    for (int k = 0; k < 8; k++) {
        ulonglong2 vA = c4[2*k];
        ulonglong2 vB = c4[2*k + 1];
        a0 = fma2(h2[4*k + 0], vA.x, a0);
        a1 = fma2(h2[4*k + 1], vA.y, a1);
        a2 = fma2(h2[4*k + 2], vB.x, a2);
        a3 = fma2(h2[4*k + 3], vB.y, a3);
    }
    a0 = add2(add2(a0, a1), add2(a2, a3));
    float2 f = unpack2(a0);
    return f.x + f.y;
}
__device__ __forceinline__ void stage64(const float* __restrict__ g, int ld,
                                        float* sW, int tid) {
#pragma unroll
    for (int r = 0; r < 32; r++) {
        int p = r * 128 + tid;
        sW[(p & 63) * SW_LD + (p >> 6)] = g[(p >> 6) * ld + (p & 63)];
    }
}

// ---------------- init kernel: zero accum/cnt + build W2T ----------------
__global__ void init_kernel(const float* __restrict__ w2) {
    int idx = blockIdx.x * 256 + threadIdx.x;
    if (idx < (NN * FEAT) / 4) ((float4*)g_accum)[idx] = make_float4(0.f, 0.f, 0.f, 0.f);
    if (idx < NN / 4)          ((float4*)g_cnt)[idx]   = make_float4(0.f, 0.f, 0.f, 0.f);
    if (idx < 64 * WN) {
        int k = idx / WN, n = idx % WN;
        g_w2t[n * 64 + PERM(k)] = __uint_as_float(f2tf32(w2[idx]));
    }
}

__global__ void finalize_kernel(const float* __restrict__ node_attr,
                                float* __restrict__ out) {
    int idx = blockIdx.x * 256 + threadIdx.x;     // float4 index
    if (idx < NN * 34) {
        int n = idx / 34;
        float inv = __frcp_rn(fmaxf(g_cnt[n], 1.0f));
        float4 a = ((const float4*)g_accum)[idx];
        float4 r = ((const float4*)node_attr)[idx];
        ((float4*)out)[idx] = make_float4(r.x + a.x * inv, r.y + a.y * inv,
                                          r.z + a.z * inv, r.w + a.w * inv);
    }
}

// ---------------- main fused kernel ----------------
__global__ void __launch_bounds__(128, 2) tp_edge_kernel(
    const float* __restrict__ node_attr,
    const int*   __restrict__ edge_index,
    const float* __restrict__ edge_attr,
    const float* __restrict__ edge_sh,
    const float* __restrict__ fc_w1,
    const float* __restrict__ fc_b1,
    const float* __restrict__ fc_b2)
{
    extern __shared__ float sm[];
    float*    sbias = sm + SB_BIAS;
    uint32_t* sH    = (uint32_t*)(sm + SB_HD);   // GEMM1 output (tf32, PERM cols)
    float*    sD    = sm + SB_HD;                // overlaid after A-frag load
    uint32_t* sB    = (uint32_t*)(sm + SB_B);    // double-buffered, stride 72

    const int tid  = threadIdx.x;
    const int lane = tid & 31;
    const int w    = tid >> 5;
    const int g    = lane >> 2;
    const int t    = lane & 3;
    const int e    = blockIdx.x * 128 + tid;
    const int src  = edge_index[e];
    const int dst  = edge_index[NE + e];

    // bias -> SMEM
    {
        float4* sb4 = (float4*)sbias;
        const float4* gb4 = (const float4*)fc_b2;
#pragma unroll 1
        for (int i = tid; i < 848; i += 128) sb4[i] = gb4[i];
    }

    // ---------- GEMM1 (scalar fp32): h = relu(ea@W1+b1) -> sH (tf32, PERM) ----------
    {
        unsigned long long ea2[32];
        const ulonglong2* gea = reinterpret_cast<const ulonglong2*>(edge_attr + (size_t)e * 64);
#pragma unroll
        for (int k = 0; k < 16; k++) { ulonglong2 v = gea[k]; ea2[2*k] = v.x; ea2[2*k+1] = v.y; }
        float* sW = sm + SB_B;        // reuse B region before pipeline
        stage64(fc_w1, 64, sW, tid);
        __syncthreads();
#pragma unroll 1
        for (int jq = 0; jq < 16; jq++) {
#pragma unroll
            for (int u = 0; u < 4; u++) {
                int j = 4 * jq + u;
                float v = dot64(ea2, &sW[j * SW_LD]) + fc_b1[j];
                sH[tid * SW_LD + PERM(j)] = f2tf32(fmaxf(v, 0.0f));
            }
        }
    }
    __syncwarp();

    // ---------- cache A fragments in registers ----------
    uint32_t a_reg[2][8][4];
#pragma unroll
    for (int mt = 0; mt < 2; mt++)
#pragma unroll
        for (int ks = 0; ks < 8; ks++) {
            uint2 p0 = *(const uint2*)&sH[(w*32 + mt*16 + g    ) * SW_LD + ks*8 + 2*t];
            uint2 p1 = *(const uint2*)&sH[(w*32 + mt*16 + g + 8) * SW_LD + ks*8 + 2*t];
            a_reg[mt][ks][0] = p0.x; a_reg[mt][ks][1] = p1.x;
            a_reg[mt][ks][2] = p0.y; a_reg[mt][ks][3] = p1.y;
        }
    __syncwarp();
    __syncthreads();   // sW (sB region) free; sH reads done

    // ---------- TP input tables (local memory) ----------
    const float* na  = node_attr + (size_t)dst * FEAT;
    const float4 shv = *reinterpret_cast<const float4*>(edge_sh + 4 * (size_t)e);
    const float sh0 = shv.x, s1x = shv.y, s1y = shv.z, s1z = shv.w;
    const float INV_S3 = 0.57735026918962576f;
    const float INV_S2 = 0.70710678118654752f;

    float oA[48], oB[192], oC[120], oD[24];
#pragma unroll 1
    for (int i = 0; i < 32; i++) oA[i] = na[i] * sh0;
#pragma unroll 1
    for (int m = 0; m < 16; m++) {
        float a0 = na[32+3*m], a1 = na[33+3*m], a2 = na[34+3*m];
        oA[32+m] = (a0*s1x + a1*s1y + a2*s1z) * INV_S3;
    }
#pragma unroll 1
    for (int i = 0; i < 32; i++) {
        float v = na[i];
        oB[3*i] = v*s1x; oB[3*i+1] = v*s1y; oB[3*i+2] = v*s1z;
    }
#pragma unroll 1
    for (int m = 0; m < 16; m++) {
        int i = 32 + m;
        oB[3*i]   = na[32+3*m] * sh0;
        oB[3*i+1] = na[33+3*m] * sh0;
        oB[3*i+2] = na[34+3*m] * sh0;
    }
#pragma unroll 1
    for (int m = 0; m < 16; m++) {
        int i = 48 + m;
        float a0 = na[80+3*m], a1 = na[81+3*m], a2 = na[82+3*m];
        oB[3*i+0] = (a1*s1z - a2*s1y) * INV_S2;
        oB[3*i+1] = (a2*s1x - a0*s1z) * INV_S2;
        oB[3*i+2] = (a0*s1y - a1*s1x) * INV_S2;
    }
#pragma unroll 1
    for (int m = 0; m < 16; m++) {
        float a0 = na[32+3*m], a1 = na[33+3*m], a2 = na[34+3*m];
        oC[3*m+0] = (a1*s1z - a2*s1y) * INV_S2;
        oC[3*m+1] = (a2*s1x - a0*s1z) * INV_S2;
        oC[3*m+2] = (a0*s1y - a1*s1x) * INV_S2;
    }
#pragma unroll 1
    for (int m = 0; m < 16; m++) {
        int i = 16 + m;
        oC[3*i]   = na[80+3*m] * sh0;
        oC[3*i+1] = na[81+3*m] * sh0;
        oC[3*i+2] = na[82+3*m] * sh0;
    }
#pragma unroll 1
    for (int m = 0; m < 8; m++) {
        int i = 32 + m; float v = na[128+m];
        oC[3*i] = v*s1x; oC[3*i+1] = v*s1y; oC[3*i+2] = v*s1z;
    }
#pragma unroll 1
    for (int m = 0; m < 16; m++) {
        float a0 = na[80+3*m], a1 = na[81+3*m], a2 = na[82+3*m];
        oD[m] = (a0*s1x + a1*s1y + a2*s1z) * INV_S3;
    }
#pragma unroll 1
    for (int m = 0; m < 8; m++) oD[16+m] = na[128+m] * sh0;

    atomicAdd(&g_cnt[src], 1.0f);
    float* yacc = g_accum + (size_t)src * FEAT;
    float* sDw  = sD + w * 32 * SW_LD;

    float acc[48];
#pragma unroll
    for (int i = 0; i < 48; i++) acc[i] = 0.0f;

    const uint32_t sB_base = smem_u32(sB);

    // prologue: async-copy chunk 0 into buffer 0
    {
#pragma unroll
        for (int i = 0; i < 8; i++) {
            int idx = i * 128 + tid;
            int n = idx >> 4, j = idx & 15;
            const float* srcp = g_w2t + (size_t)n * 64 + j * 4;
            CP_ASYNC16(sB_base + n * (SB_LD * 4) + j * 16, srcp);
        }
        CP_COMMIT();
    }

    // ---------------- 53 N-chunks of 64 ----------------
#pragma unroll 1
    for (int c = 0; c < 53; c++) {
        CP_WAIT0();
        __syncthreads();                 // chunk c visible; prev reads done

        if (c + 1 < 53) {                // async-prefetch chunk c+1 (other buffer)
            uint32_t dbase = sB_base + ((c + 1) & 1) * (64 * SB_LD * 4);
#pragma unroll
            for (int i = 0; i < 8; i++) {
                int idx = i * 128 + tid;
                int n = idx >> 4, j = idx & 15;
                const float* srcp = g_w2t + ((size_t)(c + 1) * 64 + n) * 64 + j * 4;
                CP_ASYNC16(dbase + n * (SB_LD * 4) + j * 16, srcp);
            }
            CP_COMMIT();
        }

        const uint32_t* sBc = sB + (c & 1) * (64 * SB_LD);

        // accumulators init with bias (SMEM broadcast)
        float d[2][8][4];
#pragma unroll
        for (int nt = 0; nt < 8; nt++) {
            float2 bp = *(const float2*)&sbias[c * 64 + nt * 8 + 2 * t];
#pragma unroll
            for (int mt = 0; mt < 2; mt++) {
                d[mt][nt][0] = bp.x; d[mt][nt][1] = bp.y;
                d[mt][nt][2] = bp.x; d[mt][nt][3] = bp.y;
            }
        }

        // MMA mainloop: K=64 in 8 steps, A from registers, B conflict-free (stride 72)
#pragma unroll
        for (int ks = 0; ks < 8; ks++) {
            uint32_t b[8][2];
#pragma unroll
            for (int nt = 0; nt < 8; nt++) {
                uint2 pb = *(const uint2*)&sBc[(nt*8 + g) * SB_LD + ks*8 + 2*t];
                b[nt][0] = pb.x; b[nt][1] = pb.y;
            }
#pragma unroll
            for (int mt = 0; mt < 2; mt++)
#pragma unroll
                for (int nt = 0; nt < 8; nt++)
                    mma_tf32(d[mt][nt], a_reg[mt][ks], b[nt]);
        }

        // fragments -> warp-private SMEM slice (stride 68)
#pragma unroll
        for (int mt = 0; mt < 2; mt++)
#pragma unroll
            for (int nt = 0; nt < 8; nt++) {
                *(float2*)&sDw[(mt*16 + g    ) * SW_LD + nt*8 + 2*t] = make_float2(d[mt][nt][0], d[mt][nt][1]);
                *(float2*)&sDw[(mt*16 + g + 8) * SW_LD + nt*8 + 2*t] = make_float2(d[mt][nt][2], d[mt][nt][3]);
            }
        __syncwarp();

        // own edge's 64 w-values (bias included); stride-68 LDS.128 conflict-free
        float wv[64];
#pragma unroll
        for (int u = 0; u < 16; u++) {
            float4 v = *(const float4*)&sDw[lane * SW_LD + 4 * u];
            wv[4*u] = v.x; wv[4*u+1] = v.y; wv[4*u+2] = v.z; wv[4*u+3] = v.w;
        }
        __syncwarp();

        // ---- TP contraction (register accumulators) ----
        if (c < 24) {                         // 0e
            float a0 = oA[2*c], a1 = oA[2*c + 1];
#pragma unroll
            for (int s = 0; s < 32; s++) acc[s] += a0 * wv[s] + a1 * wv[32 + s];
        } else if (c < 40) {                  // 1o
            int ib = 4 * (c - 24);
            float bx[4], by[4], bz[4];
#pragma unroll
            for (int u = 0; u < 4; u++) {
                bx[u] = oB[3*(ib+u)]; by[u] = oB[3*(ib+u)+1]; bz[u] = oB[3*(ib+u)+2];
            }
#pragma unroll
            for (int u = 0; u < 4; u++)
#pragma unroll
                for (int tt = 0; tt < 16; tt++) {
                    float wt = wv[u*16 + tt];
                    acc[tt*3+0] += bx[u] * wt; acc[tt*3+1] += by[u] * wt; acc[tt*3+2] += bz[u] * wt;
                }
        } else if (c < 50) {                  // 1e
            int ib = 4 * (c - 40);
            float bx[4], by[4], bz[4];
#pragma unroll
            for (int u = 0; u < 4; u++) {
                bx[u] = oC[3*(ib+u)]; by[u] = oC[3*(ib+u)+1]; bz[u] = oC[3*(ib+u)+2];
            }
#pragma unroll
            for (int u = 0; u < 4; u++)
#pragma unroll
                for (int tt = 0; tt < 16; tt++) {
                    float wt = wv[u*16 + tt];
                    acc[tt*3+0] += bx[u] * wt; acc[tt*3+1] += by[u] * wt; acc[tt*3+2] += bz[u] * wt;
                }
        } else {                              // 0o
            int ib = 8 * (c - 50);
            float av[8];
#pragma unroll
            for (int u = 0; u < 8; u++) av[u] = oD[ib + u];
#pragma unroll
            for (int u = 0; u < 8; u++)
#pragma unroll
                for (int tt = 0; tt < 8; tt++) acc[tt] += av[u] * wv[u*8 + tt];
        }

        // phase-boundary flushes (fully unrolled -> acc stays in registers)
        if (c == 23) {
#pragma unroll
            for (int o = 0; o < 32; o++) atomicAdd(yacc + o, acc[o] * 0.14433756729740643f);
#pragma unroll
            for (int i = 0; i < 48; i++) acc[i] = 0.0f;
        } else if (c == 39) {
#pragma unroll
            for (int q = 0; q < 48; q++) atomicAdd(yacc + 32 + q, acc[q] * 0.125f);
#pragma unroll
            for (int i = 0; i < 48; i++) acc[i] = 0.0f;
        } else if (c == 49) {
#pragma unroll
            for (int q = 0; q < 48; q++) atomicAdd(yacc + 80 + q, acc[q] * 0.15811388300841897f);
#pragma unroll
            for (int i = 0; i < 48; i++) acc[i] = 0.0f;
        } else if (c == 52) {
#pragma unroll
            for (int o = 0; o < 8; o++) atomicAdd(yacc + 128 + o, acc[o] * 0.20412414523193150f);
        }
    }
}

extern "C" void kernel_launch(void* const* d_in, const int* in_sizes, int n_in,
                              void* d_out, int out_size) {
    const float* node_attr  = (const float*)d_in[0];
    const int*   edge_index = (const int*)  d_in[1];
    const float* edge_attr  = (const float*)d_in[2];
    const float* edge_sh    = (const float*)d_in[3];
    const float* fc_w1      = (const float*)d_in[4];
    const float* fc_b1      = (const float*)d_in[5];
    const float* fc_w2      = (const float*)d_in[6];
    const float* fc_b2      = (const float*)d_in[7];
    float* out = (float*)d_out;

    cudaFuncSetAttribute(tp_edge_kernel, cudaFuncAttributeMaxDynamicSharedMemorySize, SMEM_BYTES);

    init_kernel<<<((NN * FEAT) / 4 + 255) / 256, 256>>>(fc_w2);
    tp_edge_kernel<<<NE / 128, 128, SMEM_BYTES>>>(node_attr, edge_index, edge_attr,
                                                  edge_sh, fc_w1, fc_b1, fc_b2);
    finalize_kernel<<<(NN * 34 + 255) / 256, 256>>>(node_attr, out);
}